// round 6
// baseline (speedup 1.0000x reference)
#include <cuda_runtime.h>
#include <math.h>

#define NPTS   4096
#define NBATCH 16
#define NSAMP  1024
#define NK     32
#define NROWS  (NBATCH*NSAMP*NK)      /* 524288 */
#define NSAMPT (NBATCH*NSAMP)         /* 16384  */
#define OUT_OFF (NBATCH*NSAMP*3)      /* 49152  */

// ---------------- device scratch (no allocations allowed) ----------------
__device__ float  g_centroids[NBATCH*NSAMP*3];
__device__ float  g_x0[(size_t)NROWS*68];
__device__ float  g_y0[(size_t)NROWS*64];
__device__ float  g_y1[(size_t)NROWS*64];
__device__ float  g_ymax[(size_t)NSAMPT*128];
__device__ float  g_ymin[(size_t)NSAMPT*128];
__device__ double g_sums[512];
__device__ float  g_scale[256];
__device__ float  g_shift[256];

__global__ void zero_stats_kernel() {
    int t = threadIdx.x;
    if (t < 512) g_sums[t] = 0.0;
}

// ---------------- packed f32x2 helpers (exact RN f32 math) ---------------
__device__ __forceinline__ unsigned long long pk_dup(float x) {
    unsigned long long r; unsigned u = __float_as_uint(x);
    asm("mov.b64 %0, {%1, %1};" : "=l"(r) : "r"(u));
    return r;
}
__device__ __forceinline__ void fma2(unsigned long long& d, unsigned long long a,
                                     unsigned long long b) {
    asm("fma.rn.f32x2 %0, %1, %2, %0;" : "+l"(d) : "l"(a), "l"(b));
}
__device__ __forceinline__ void unpk(unsigned long long v, float& lo, float& hi) {
    unsigned a, b;
    asm("mov.b64 {%0, %1}, %2;" : "=r"(a), "=r"(b) : "l"(v));
    lo = __uint_as_float(a); hi = __uint_as_float(b);
}

// ============================ FPS =========================================
// dist = min(dist, |p-c|^2); far = argmax (first index on tie).
// Points cached in dynamic smem (SoA). One __syncthreads per iteration via
// double-buffered per-warp reduction slots. REDUX (32-bit) reductions:
// max on dist-bits, then max on masked (4095-idx) -> exact first-index tie.
// Float update lines verbatim from the bit-exact prior versions.
__global__ __launch_bounds__(1024) void fps_kernel(const float* __restrict__ data,
                                                   const int* __restrict__ initf,
                                                   float* __restrict__ out) {
    extern __shared__ float fsm[];
    float* s_px = fsm;               // 4096
    float* s_py = fsm + NPTS;        // 4096
    float* s_pz = fsm + 2*NPTS;      // 4096
    unsigned* s_rd = (unsigned*)(fsm + 3*NPTS);   // 64 (double-buffered)
    unsigned* s_ri = s_rd + 64;                   // 64

    const int b = blockIdx.x, tid = threadIdx.x;
    const int lane = tid & 31, wid = tid >> 5;
    const float* db = data + (size_t)b * NPTS * 3;

    float px[4], py[4], pz[4], dist[4];
#pragma unroll
    for (int i = 0; i < 4; i++) {
        int n = tid + i * 1024;
        float x = db[n*3+0], y = db[n*3+1], z = db[n*3+2];
        px[i] = x; py[i] = y; pz[i] = z;
        s_px[n] = x; s_py[n] = y; s_pz[n] = z;
        dist[i] = 1e10f;
    }
    int far = __ldg(initf + b);
    __syncthreads();

    for (int s = 0; s < NSAMP; s++) {
        float cx = s_px[far], cy = s_py[far], cz = s_pz[far];
        if (tid == 0) {
            int o = (b*NSAMP + s) * 3;
            out[o] = cx; out[o+1] = cy; out[o+2] = cz;
            g_centroids[o] = cx; g_centroids[o+1] = cy; g_centroids[o+2] = cz;
        }
        unsigned long long best = 0ull;
#pragma unroll
        for (int i = 0; i < 4; i++) {
            float dx = px[i]-cx, dy = py[i]-cy, dz = pz[i]-cz;
            float d = dx*dx + dy*dy + dz*dz;
            dist[i] = fminf(dist[i], d);
            unsigned long long key =
                ((unsigned long long)__float_as_uint(dist[i]) << 32) |
                (unsigned)(4095 - (tid + i*1024));
            best = best > key ? best : key;
        }
        unsigned d32 = (unsigned)(best >> 32);
        unsigned i32 = (unsigned)best;
        unsigned wd = __reduce_max_sync(0xffffffffu, d32);
        unsigned ci = (d32 == wd) ? i32 : 0u;
        unsigned wi = __reduce_max_sync(0xffffffffu, ci);
        int par = (s & 1) * 32;
        if (lane == 0) { s_rd[par + wid] = wd; s_ri[par + wid] = wi; }
        __syncthreads();
        unsigned dv = s_rd[par + lane], iv = s_ri[par + lane];
        unsigned gd = __reduce_max_sync(0xffffffffu, dv);
        unsigned c2 = (dv == gd) ? iv : 0u;
        unsigned gi = __reduce_max_sync(0xffffffffu, c2);
        far = 4095 - (int)gi;
    }
}

// ==================== stage 2+3: top64 -> top32 -> x0 rows ================
struct Stage3 {
    float px[64], py[64], pz[64];
    unsigned long long sk[64];
    float snx[32], sny[32], snz[32], zw[32];
    int   tk[32];
};

__device__ __forceinline__ unsigned ord_f32(float v) {
    unsigned u = __float_as_uint(v);
    return (u & 0x80000000u) ? ~u : (u | 0x80000000u);
}

// Bit-exact replication of the reference square-dist (verified passing):
__device__ __forceinline__ float sqdist_ref(float cx, float cy, float cz, float an2,
                                            float x, float y, float z) {
    float e   = __fmaf_rn(cz, z, __fmaf_rn(cy, y, __fmul_rn(cx, x)));
    float bn2 = __fadd_rn(__fadd_rn(__fmul_rn(x, x), __fmul_rn(y, y)), __fmul_rn(z, z));
    return __fadd_rn(__fadd_rn(__fmul_rn(-2.f, e), an2), bn2);
}

__global__ __launch_bounds__(256) void build_kernel(const float* __restrict__ data,
                                                    const float* __restrict__ feat) {
    extern __shared__ char bsm[];
    unsigned long long* s_keys = (unsigned long long*)bsm;            // 4096 * 8
    unsigned int*       s_hist = (unsigned int*)(bsm + 32768);        // 4096 * 4
    unsigned long long* s_cand = (unsigned long long*)(bsm + 49152);  // 1024 * 8
    int*                s_tot  = (int*)(bsm + 57344);                 // 256 * 4
    int*                s_ctl  = (int*)(bsm + 58368);                 // [0]=T [1]=m

    const int tid = threadIdx.x;
    const int b = blockIdx.x >> 10, s = blockIdx.x & 1023;
    const float* db = data + (size_t)b * NPTS * 3;
    const int co = (b*NSAMP + s) * 3;
    const float cx = g_centroids[co], cy = g_centroids[co+1], cz = g_centroids[co+2];
    const float an2 = __fadd_rn(__fadd_rn(__fmul_rn(cx, cx), __fmul_rn(cy, cy)),
                                __fmul_rn(cz, cz));

    for (int i = tid; i < 4096; i += 256) s_hist[i] = 0u;
    if (tid == 0) s_ctl[1] = 0;
    __syncthreads();

    // pass 1: compute keys once, cache in smem, histogram top 12 bits
    for (int i = 0; i < 16; i++) {
        int n = tid + i * 256;
        float x = db[n*3], y = db[n*3+1], z = db[n*3+2];
        float v = sqdist_ref(cx, cy, cz, an2, x, y, z);
        unsigned u = ord_f32(v);
        s_keys[n] = ((unsigned long long)u << 32) | (unsigned)(4095 - n);
        atomicAdd(&s_hist[u >> 20], 1u);
    }
    __syncthreads();

    // suffix counts over 256 chunks of 16 bins
    unsigned tot = 0;
    for (int j = 0; j < 16; j++) tot += s_hist[tid*16 + j];
    s_tot[tid] = (int)tot;
    __syncthreads();
    for (int off = 1; off < 256; off <<= 1) {
        int add = (tid + off < 256) ? s_tot[tid + off] : 0;
        __syncthreads();
        s_tot[tid] += add;
        __syncthreads();
    }
    unsigned cum = (tid < 255) ? (unsigned)s_tot[tid + 1] : 0u;
    for (int j = 15; j >= 0; j--) {
        unsigned h = s_hist[tid*16 + j];
        if (cum < 64u && cum + h >= 64u) s_ctl[0] = tid*16 + j;   // unique crossing
        cum += h;
    }
    __syncthreads();
    const unsigned T = (unsigned)s_ctl[0];

    // pass 2: pure smem scan, push candidates with bin >= T
    for (int i = 0; i < 16; i++) {
        int n = tid + i * 256;
        unsigned long long key = s_keys[n];
        if ((unsigned)(key >> 52) >= T) {
            int slot = atomicAdd(&s_ctl[1], 1);
            if (slot < 1024) s_cand[slot] = key;
        }
    }
    __syncthreads();
    int M = s_ctl[1]; if (M > 1024) M = 1024;
    int P = 64; while (P < M) P <<= 1;
    for (int i = M + tid; i < P; i += 256) s_cand[i] = 0ull;

    // bitonic sort descending
    for (int k = 2; k <= P; k <<= 1)
        for (int j = k >> 1; j > 0; j >>= 1) {
            __syncthreads();
            for (int i = tid; i < P; i += 256) {
                int ix = i ^ j;
                if (ix > i) {
                    unsigned long long a = s_cand[i], c = s_cand[ix];
                    if (((i & k) == 0) ? (a < c) : (a > c)) { s_cand[i] = c; s_cand[ix] = a; }
                }
            }
        }
    __syncthreads();

    Stage3* st = (Stage3*)s_hist;   // alias dead histogram
    if (tid < 64) {
        int id = 4095 - (int)(unsigned)(s_cand[tid] & 0xFFFFFFFFull);
        st->px[tid] = db[id*3]; st->py[tid] = db[id*3+1]; st->pz[tid] = db[id*3+2];
    }
    __syncthreads();
    if (tid < 64) {
        float sc = fabsf(st->pz[tid] - st->pz[(tid + 63) & 63]);   // roll(+1)
        st->sk[tid] = ((unsigned long long)__float_as_uint(sc) << 32) | (unsigned)(63 - tid);
    }
    for (int k = 2; k <= 64; k <<= 1)
        for (int j = k >> 1; j > 0; j >>= 1) {
            __syncthreads();
            if (tid < 64) {
                int i = tid, ix = i ^ j;
                if (ix > i) {
                    unsigned long long a = st->sk[i], c = st->sk[ix];
                    if (((i & k) == 0) ? (a < c) : (a > c)) { st->sk[i] = c; st->sk[ix] = a; }
                }
            }
        }
    __syncthreads();

    if (tid < 32) {
        int j = 63 - (int)(unsigned)(st->sk[tid] & 63ull);   // tki
        float sx = st->px[j] - cx, sy = st->py[j] - cy, sz = st->pz[j] - cz;
        float w = fabsf(st->pz[j] - cz);
        float m = w;
#pragma unroll
        for (int off = 16; off; off >>= 1) m = fmaxf(m, __shfl_xor_sync(0xffffffffu, m, off));
        float e = expf(w - m);
        float su = e;
#pragma unroll
        for (int off = 16; off; off >>= 1) su += __shfl_xor_sync(0xffffffffu, su, off);
        st->snx[tid] = sx; st->sny[tid] = sy; st->snz[tid] = sz;
        st->zw[tid] = e / su;
        st->tk[tid] = j;
    }
    __syncthreads();

    size_t R0 = (size_t)(b*NSAMP + s) * NK;
    for (int e = tid; e < NK * 68; e += 256) {
        int k = e / 68, c = e - k * 68;
        float val;
        if (c < 3)        val = (c == 0 ? st->snx[k] : (c == 1 ? st->sny[k] : st->snz[k])) * st->zw[k];
        else if (c < 67)  val = feat[((size_t)b*NPTS + st->tk[k]) * 64 + (c - 3)] * st->zw[k];
        else              val = 0.f;
        g_x0[(R0 + k) * 68 + c] = val;
    }
}

// ======== GEMM layers 0/1: 4 rows x 16 cols per thread, f32x2 =============
// 256 threads: warp w -> col-group cg = w&3 (16 cols), half = w>>2 (128 rows).
// Per k: 1 LDS.128 x (conflict-free, stride 4) + 2 broadcast LDS.128 w
// (8 packed col-pairs) -> 32 fma2. Per-element k-chain identical to prior
// rounds -> bit-exact y.
template<int LAYER>
__global__ __launch_bounds__(256, 2) void gemm01_kernel(const float* __restrict__ W,
                                                        const float* __restrict__ bias) {
    constexpr int KIN   = (LAYER == 0) ? 68 : 64;
    constexpr int KREAL = (LAYER == 0) ? 67 : 64;
    constexpr int OUT   = 64;
    constexpr int RPB   = 256;
    constexpr int XS    = RPB + 4;

    extern __shared__ float sm[];
    float* s_x = sm;                                        // [KIN][XS]
    unsigned long long* s_w2 = (unsigned long long*)(sm + KIN * XS);  // [KIN][32] col-pairs

    const float* X = (LAYER == 0) ? g_x0 : g_y0;
    float*       Y = (LAYER == 0) ? g_y0 : g_y1;
    double* sums = g_sums + ((LAYER == 0) ? 0 : 128);

    const int tid = threadIdx.x;
    const int wid = tid >> 5, lane = tid & 31;
    const int cg = wid & 3;            // cols cg*16 .. +15
    const int rbase = (wid >> 2) * 128 + 4 * lane;   // 4 rows
    const size_t row0 = (size_t)blockIdx.x * RPB;

    // stage w as packed col-pairs: s_w2[k*32 + c2] = (W[2c2][k], W[2c2+1][k])
    for (int i = tid; i < KIN * 32; i += 256) {
        int k = i >> 5, c2 = i & 31;
        float wa = (k < KREAL) ? W[(2*c2)   * KREAL + k] : 0.f;
        float wb = (k < KREAL) ? W[(2*c2+1) * KREAL + k] : 0.f;
        unsigned long long p;
        asm("mov.b64 %0, {%1, %2};" : "=l"(p) : "r"(__float_as_uint(wa)), "r"(__float_as_uint(wb)));
        s_w2[i] = p;
    }
    // stage x transposed (vectorized gmem reads; KIN % 4 == 0)
    for (int i4 = tid; i4 < RPB * (KIN/4); i4 += 256) {
        int r = i4 / (KIN/4), kq = (i4 % (KIN/4)) * 4;
        float4 v = *(const float4*)&X[(row0 + r) * KIN + kq];
        if (LAYER > 0) {
            v.x = fmaxf(fmaf(v.x, __ldg(&g_scale[kq+0]), __ldg(&g_shift[kq+0])), 0.f);
            v.y = fmaxf(fmaf(v.y, __ldg(&g_scale[kq+1]), __ldg(&g_shift[kq+1])), 0.f);
            v.z = fmaxf(fmaf(v.z, __ldg(&g_scale[kq+2]), __ldg(&g_shift[kq+2])), 0.f);
            v.w = fmaxf(fmaf(v.w, __ldg(&g_scale[kq+3]), __ldg(&g_shift[kq+3])), 0.f);
        }
        s_x[(kq+0)*XS + r] = v.x; s_x[(kq+1)*XS + r] = v.y;
        s_x[(kq+2)*XS + r] = v.z; s_x[(kq+3)*XS + r] = v.w;
    }
    __syncthreads();

    unsigned long long acc[4][8];
#pragma unroll
    for (int r = 0; r < 4; r++)
#pragma unroll
        for (int j = 0; j < 8; j++) acc[r][j] = 0ull;

#pragma unroll 4
    for (int k = 0; k < KIN; k++) {
        float4 xq = *(const float4*)(s_x + k * XS + rbase);
        unsigned long long a0 = pk_dup(xq.x), a1 = pk_dup(xq.y),
                           a2 = pk_dup(xq.z), a3 = pk_dup(xq.w);
        ulonglong2 w01 = *(const ulonglong2*)(s_w2 + k * 32 + cg * 8);
        ulonglong2 w23 = *(const ulonglong2*)(s_w2 + k * 32 + cg * 8 + 2);
        ulonglong2 w45 = *(const ulonglong2*)(s_w2 + k * 32 + cg * 8 + 4);
        ulonglong2 w67 = *(const ulonglong2*)(s_w2 + k * 32 + cg * 8 + 6);
        fma2(acc[0][0], a0, w01.x); fma2(acc[0][1], a0, w01.y);
        fma2(acc[0][2], a0, w23.x); fma2(acc[0][3], a0, w23.y);
        fma2(acc[0][4], a0, w45.x); fma2(acc[0][5], a0, w45.y);
        fma2(acc[0][6], a0, w67.x); fma2(acc[0][7], a0, w67.y);
        fma2(acc[1][0], a1, w01.x); fma2(acc[1][1], a1, w01.y);
        fma2(acc[1][2], a1, w23.x); fma2(acc[1][3], a1, w23.y);
        fma2(acc[1][4], a1, w45.x); fma2(acc[1][5], a1, w45.y);
        fma2(acc[1][6], a1, w67.x); fma2(acc[1][7], a1, w67.y);
        fma2(acc[2][0], a2, w01.x); fma2(acc[2][1], a2, w01.y);
        fma2(acc[2][2], a2, w23.x); fma2(acc[2][3], a2, w23.y);
        fma2(acc[2][4], a2, w45.x); fma2(acc[2][5], a2, w45.y);
        fma2(acc[2][6], a2, w67.x); fma2(acc[2][7], a2, w67.y);
        fma2(acc[3][0], a3, w01.x); fma2(acc[3][1], a3, w01.y);
        fma2(acc[3][2], a3, w23.x); fma2(acc[3][3], a3, w23.y);
        fma2(acc[3][4], a3, w45.x); fma2(acc[3][5], a3, w45.y);
        fma2(acc[3][6], a3, w67.x); fma2(acc[3][7], a3, w67.y);
    }

    float bl[16];
#pragma unroll
    for (int j = 0; j < 16; j++) bl[j] = bias[cg * 16 + j];
    float psum[16], psq[16];
#pragma unroll
    for (int j = 0; j < 16; j++) { psum[j] = 0.f; psq[j] = 0.f; }

#pragma unroll
    for (int r = 0; r < 4; r++) {
        float yv[16];
#pragma unroll
        for (int jp = 0; jp < 8; jp++) unpk(acc[r][jp], yv[2*jp], yv[2*jp+1]);
#pragma unroll
        for (int j = 0; j < 16; j++) {
            yv[j] = yv[j] + bl[j];
            psum[j] += yv[j];
            psq[j]  = fmaf(yv[j], yv[j], psq[j]);
        }
        size_t row = row0 + rbase + r;
        float4* dst = (float4*)&Y[row * OUT + cg * 16];
        dst[0] = make_float4(yv[0],  yv[1],  yv[2],  yv[3]);
        dst[1] = make_float4(yv[4],  yv[5],  yv[6],  yv[7]);
        dst[2] = make_float4(yv[8],  yv[9],  yv[10], yv[11]);
        dst[3] = make_float4(yv[12], yv[13], yv[14], yv[15]);
    }
#pragma unroll
    for (int j = 0; j < 16; j++) {
#pragma unroll
        for (int off = 16; off; off >>= 1) {
            psum[j] += __shfl_down_sync(0xffffffffu, psum[j], off);
            psq[j]  += __shfl_down_sync(0xffffffffu, psq[j],  off);
        }
    }
    if (lane == 0) {
#pragma unroll
        for (int j = 0; j < 16; j++) {
            atomicAdd(&sums[cg * 16 + j],       (double)psum[j]);
            atomicAdd(&sums[OUT + cg * 16 + j], (double)psq[j]);
        }
    }
}

// ======== GEMM layer 2: 4 rows x 16 cols, stats + per-sample max/min ======
__global__ __launch_bounds__(256, 2) void gemm2_kernel(const float* __restrict__ W,
                                                       const float* __restrict__ bias) {
    constexpr int KIN = 64, OUT = 128, RPB = 128, XS = RPB + 4;

    extern __shared__ float sm[];
    float* s_x = sm;                                        // [64][132]
    unsigned long long* s_w2 = (unsigned long long*)(sm + KIN * XS);  // [64][64]
    double* sums = g_sums + 256;

    const int tid = threadIdx.x;
    const int wid = tid >> 5, lane = tid & 31;
    const int cg = wid;                 // 8 warps x 16 cols = 128
    const int rbase = 4 * lane;         // 4 rows, 128 rows total
    const size_t row0 = (size_t)blockIdx.x * RPB;

    for (int i = tid; i < KIN * 64; i += 256) {
        int k = i >> 6, c2 = i & 63;
        float wa = W[(2*c2)   * KIN + k];
        float wb = W[(2*c2+1) * KIN + k];
        unsigned long long p;
        asm("mov.b64 %0, {%1, %2};" : "=l"(p) : "r"(__float_as_uint(wa)), "r"(__float_as_uint(wb)));
        s_w2[i] = p;
    }
    for (int i4 = tid; i4 < RPB * (KIN/4); i4 += 256) {
        int r = i4 / (KIN/4), kq = (i4 % (KIN/4)) * 4;
        float4 v = *(const float4*)&g_y1[(row0 + r) * KIN + kq];
        v.x = fmaxf(fmaf(v.x, __ldg(&g_scale[64+kq+0]), __ldg(&g_shift[64+kq+0])), 0.f);
        v.y = fmaxf(fmaf(v.y, __ldg(&g_scale[64+kq+1]), __ldg(&g_shift[64+kq+1])), 0.f);
        v.z = fmaxf(fmaf(v.z, __ldg(&g_scale[64+kq+2]), __ldg(&g_shift[64+kq+2])), 0.f);
        v.w = fmaxf(fmaf(v.w, __ldg(&g_scale[64+kq+3]), __ldg(&g_shift[64+kq+3])), 0.f);
        s_x[(kq+0)*XS + r] = v.x; s_x[(kq+1)*XS + r] = v.y;
        s_x[(kq+2)*XS + r] = v.z; s_x[(kq+3)*XS + r] = v.w;
    }
    __syncthreads();

    unsigned long long acc[4][8];
#pragma unroll
    for (int r = 0; r < 4; r++)
#pragma unroll
        for (int j = 0; j < 8; j++) acc[r][j] = 0ull;

#pragma unroll 4
    for (int k = 0; k < KIN; k++) {
        float4 xq = *(const float4*)(s_x + k * XS + rbase);
        unsigned long long a0 = pk_dup(xq.x), a1 = pk_dup(xq.y),
                           a2 = pk_dup(xq.z), a3 = pk_dup(xq.w);
        ulonglong2 w01 = *(const ulonglong2*)(s_w2 + k * 64 + cg * 8);
        ulonglong2 w23 = *(const ulonglong2*)(s_w2 + k * 64 + cg * 8 + 2);
        ulonglong2 w45 = *(const ulonglong2*)(s_w2 + k * 64 + cg * 8 + 4);
        ulonglong2 w67 = *(const ulonglong2*)(s_w2 + k * 64 + cg * 8 + 6);
        fma2(acc[0][0], a0, w01.x); fma2(acc[0][1], a0, w01.y);
        fma2(acc[0][2], a0, w23.x); fma2(acc[0][3], a0, w23.y);
        fma2(acc[0][4], a0, w45.x); fma2(acc[0][5], a0, w45.y);
        fma2(acc[0][6], a0, w67.x); fma2(acc[0][7], a0, w67.y);
        fma2(acc[1][0], a1, w01.x); fma2(acc[1][1], a1, w01.y);
        fma2(acc[1][2], a1, w23.x); fma2(acc[1][3], a1, w23.y);
        fma2(acc[1][4], a1, w45.x); fma2(acc[1][5], a1, w45.y);
        fma2(acc[1][6], a1, w67.x); fma2(acc[1][7], a1, w67.y);
        fma2(acc[2][0], a2, w01.x); fma2(acc[2][1], a2, w01.y);
        fma2(acc[2][2], a2, w23.x); fma2(acc[2][3], a2, w23.y);
        fma2(acc[2][4], a2, w45.x); fma2(acc[2][5], a2, w45.y);
        fma2(acc[2][6], a2, w67.x); fma2(acc[2][7], a2, w67.y);
        fma2(acc[3][0], a3, w01.x); fma2(acc[3][1], a3, w01.y);
        fma2(acc[3][2], a3, w23.x); fma2(acc[3][3], a3, w23.y);
        fma2(acc[3][4], a3, w45.x); fma2(acc[3][5], a3, w45.y);
        fma2(acc[3][6], a3, w67.x); fma2(acc[3][7], a3, w67.y);
    }

    float bl[16];
#pragma unroll
    for (int j = 0; j < 16; j++) bl[j] = bias[cg * 16 + j];
    float psum[16], psq[16], tmax[16], tmin[16];
#pragma unroll
    for (int j = 0; j < 16; j++) {
        psum[j] = 0.f; psq[j] = 0.f; tmax[j] = -1e30f; tmin[j] = 1e30f;
    }

#pragma unroll
    for (int r = 0; r < 4; r++) {
        float yv[16];
#pragma unroll
        for (int jp = 0; jp < 8; jp++) unpk(acc[r][jp], yv[2*jp], yv[2*jp+1]);
#pragma unroll
        for (int j = 0; j < 16; j++) {
            yv[j] = yv[j] + bl[j];
            psum[j] += yv[j];
            psq[j]  = fmaf(yv[j], yv[j], psq[j]);
            tmax[j] = fmaxf(tmax[j], yv[j]);
            tmin[j] = fminf(tmin[j], yv[j]);
        }
    }
    // stats over 128 rows (full warp covers all rows for these 16 cols)
#pragma unroll
    for (int j = 0; j < 16; j++) {
#pragma unroll
        for (int off = 16; off; off >>= 1) {
            psum[j] += __shfl_down_sync(0xffffffffu, psum[j], off);
            psq[j]  += __shfl_down_sync(0xffffffffu, psq[j],  off);
        }
    }
    if (lane == 0) {
#pragma unroll
        for (int j = 0; j < 16; j++) {
            atomicAdd(&sums[cg * 16 + j],       (double)psum[j]);
            atomicAdd(&sums[OUT + cg * 16 + j], (double)psq[j]);
        }
    }
    // per-sample (32 rows) max/min: lanes 8m..8m+7 cover sample m
#pragma unroll
    for (int j = 0; j < 16; j++) {
#pragma unroll
        for (int off = 4; off; off >>= 1) {
            tmax[j] = fmaxf(tmax[j], __shfl_down_sync(0xffffffffu, tmax[j], off, 8));
            tmin[j] = fminf(tmin[j], __shfl_down_sync(0xffffffffu, tmin[j], off, 8));
        }
    }
    if ((lane & 7) == 0) {
        size_t samp = row0 / 32 + (lane >> 3);
        float4* pma = (float4*)&g_ymax[samp * 128 + cg * 16];
        float4* pmi = (float4*)&g_ymin[samp * 128 + cg * 16];
        pma[0] = make_float4(tmax[0],  tmax[1],  tmax[2],  tmax[3]);
        pma[1] = make_float4(tmax[4],  tmax[5],  tmax[6],  tmax[7]);
        pma[2] = make_float4(tmax[8],  tmax[9],  tmax[10], tmax[11]);
        pma[3] = make_float4(tmax[12], tmax[13], tmax[14], tmax[15]);
        pmi[0] = make_float4(tmin[0],  tmin[1],  tmin[2],  tmin[3]);
        pmi[1] = make_float4(tmin[4],  tmin[5],  tmin[6],  tmin[7]);
        pmi[2] = make_float4(tmin[8],  tmin[9],  tmin[10], tmin[11]);
        pmi[3] = make_float4(tmin[12], tmin[13], tmin[14], tmin[15]);
    }
}

__global__ void finalize_kernel(const float* __restrict__ g, const float* __restrict__ be,
                                int O, int soff, int scoff) {
    int c = threadIdx.x;
    if (c >= O) return;
    double n = (double)NROWS;
    double mean = g_sums[soff + c] / n;
    double var  = g_sums[soff + O + c] / n - mean * mean;
    double sc   = (double)g[c] * rsqrt(var + 1e-5);
    g_scale[scoff + c] = (float)sc;
    g_shift[scoff + c] = (float)((double)be[c] - mean * sc);
}

// maxpool via pre-reduced max/min: relu(fma(y,sc,sh)) monotone in y for
// fixed sign(sc) -> exact.
__global__ __launch_bounds__(128) void maxpool_kernel(float* __restrict__ out) {
    int bs = blockIdx.x, c = threadIdx.x;
    float sc = g_scale[128 + c], sh = g_shift[128 + c];
    float v = (sc >= 0.f) ? g_ymax[(size_t)bs * 128 + c] : g_ymin[(size_t)bs * 128 + c];
    out[OUT_OFF + (size_t)bs * 128 + c] = fmaxf(fmaf(v, sc, sh), 0.f);
}

// ============================ launcher ====================================
extern "C" void kernel_launch(void* const* d_in, const int* in_sizes, int n_in,
                              void* d_out, int out_size) {
    const float* data = (const float*)d_in[0];
    const float* feat = (const float*)d_in[1];
    const int*   initf = (const int*)d_in[2];
    const float* W0 = (const float*)d_in[3];  const float* b0 = (const float*)d_in[4];
    const float* g0 = (const float*)d_in[5];  const float* be0 = (const float*)d_in[6];
    const float* W1 = (const float*)d_in[7];  const float* b1 = (const float*)d_in[8];
    const float* g1 = (const float*)d_in[9];  const float* be1 = (const float*)d_in[10];
    const float* W2 = (const float*)d_in[11]; const float* b2 = (const float*)d_in[12];
    const float* g2 = (const float*)d_in[13]; const float* be2 = (const float*)d_in[14];
    float* out = (float*)d_out;

    const int smf = NPTS * 3 * 4 + 128 * 4;          // fps: 49664
    const int smb = 58368 + 32;                      // build
    const int sm0 = 68*260*4 + 68*32*8;              // 88128
    const int sm1 = 64*260*4 + 64*32*8;              // 82944
    const int sm2 = 64*132*4 + 64*64*8;              // 66560
    cudaFuncSetAttribute((const void*)fps_kernel,       cudaFuncAttributeMaxDynamicSharedMemorySize, smf);
    cudaFuncSetAttribute((const void*)build_kernel,     cudaFuncAttributeMaxDynamicSharedMemorySize, smb);
    cudaFuncSetAttribute((const void*)gemm01_kernel<0>, cudaFuncAttributeMaxDynamicSharedMemorySize, sm0);
    cudaFuncSetAttribute((const void*)gemm01_kernel<1>, cudaFuncAttributeMaxDynamicSharedMemorySize, sm1);
    cudaFuncSetAttribute((const void*)gemm2_kernel,     cudaFuncAttributeMaxDynamicSharedMemorySize, sm2);

    zero_stats_kernel<<<1, 512>>>();
    fps_kernel<<<NBATCH, 1024, smf>>>(data, initf, out);
    build_kernel<<<NBATCH * NSAMP, 256, smb>>>(data, feat);
    gemm01_kernel<0><<<NROWS / 256, 256, sm0>>>(W0, b0);
    finalize_kernel<<<1, 128>>>(g0, be0, 64, 0, 0);
    gemm01_kernel<1><<<NROWS / 256, 256, sm1>>>(W1, b1);
    finalize_kernel<<<1, 128>>>(g1, be1, 64, 128, 64);
    gemm2_kernel<<<NROWS / 128, 256, sm2>>>(W2, b2);
    finalize_kernel<<<1, 128>>>(g2, be2, 128, 256, 128);
    maxpool_kernel<<<NBATCH * NSAMP, 128>>>(out);
}